// round 1
// baseline (speedup 1.0000x reference)
#include <cuda_runtime.h>
#include <math.h>

#define WPB   16          // warps (= samples) per block
#define KPT   133
#define PTS3  399

__device__ double g_acc;

__global__ void k_zero() { g_acc = 0.0; }

__global__ void k_final(float* __restrict__ out, double inv_cnt) {
    out[0] = (float)(g_acc * inv_cnt);
}

__device__ __forceinline__ float warp_sum(float v) {
#pragma unroll
    for (int o = 16; o > 0; o >>= 1) v += __shfl_xor_sync(0xffffffffu, v, o);
    return v;
}

// One cyclic-Jacobi rotation in the (p,q) plane of symmetric B, with the single
// off-plane element pair (bkp,bkq) and the V columns (p,q) updated.
__device__ __forceinline__ void jrot(float& app, float& aqq, float& apq,
                                     float& bkp, float& bkq,
                                     float& vp0, float& vq0,
                                     float& vp1, float& vq1,
                                     float& vp2, float& vq2)
{
    float a = apq;
    if (fabsf(a) > 1e-30f) {
        float theta = 0.5f * (aqq - app) / a;
        float t = copysignf(1.f, theta) / (fabsf(theta) + sqrtf(theta * theta + 1.f));
        float c = rsqrtf(t * t + 1.f);
        float s = t * c;
        app -= t * a;
        aqq += t * a;
        apq = 0.f;
        float t0 = bkp, t1 = bkq;
        bkp = c * t0 - s * t1;  bkq = s * t0 + c * t1;
        t0 = vp0; t1 = vq0; vp0 = c * t0 - s * t1; vq0 = s * t0 + c * t1;
        t0 = vp1; t1 = vq1; vp1 = c * t0 - s * t1; vq1 = s * t0 + c * t1;
        t0 = vp2; t1 = vq2; vp2 = c * t0 - s * t1; vq2 = s * t0 + c * t1;
    }
}

#define CSWAP(la, lb, x0, x1, y0, y1, z0, z1) \
    { float _t; _t = la; la = lb; lb = _t; _t = x0; x0 = x1; x1 = _t; \
      _t = y0; y0 = y1; y1 = _t; _t = z0; z0 = z1; z1 = _t; }

__global__ void __launch_bounds__(WPB * 32, 2)
k_pa(const float* __restrict__ g_outp, const float* __restrict__ g_tgtp, int n)
{
    extern __shared__ float dyn[];
    float* sh_o    = dyn;                        // [WPB][PTS3]
    float* sh_t    = dyn + WPB * PTS3;           // [WPB][PTS3]
    float* sh_task = dyn + 2 * WPB * PTS3;       // [WPB][16]: K(9), var1, mu1(3), mu2(3)
    float* sh_res  = sh_task + WPB * 16;         // [WPB][16]: R(9), scale, mu1(3), mu2(3)

    const int w      = threadIdx.x >> 5;
    const int lane   = threadIdx.x & 31;
    const int sample = blockIdx.x * WPB + w;
    const bool valid = (sample < n);

    float* p_o = sh_o + w * PTS3;
    float* p_t = sh_t + w * PTS3;

    // ---------------- Phase A: stage + per-sample reductions ----------------
    if (valid) {
        const float* go = g_outp + (size_t)sample * PTS3;
        const float* gt = g_tgtp + (size_t)sample * PTS3;
        for (int i = lane; i < PTS3; i += 32) {
            p_o[i] = go[i];
            p_t[i] = gt[i];
        }
        __syncwarp();

        float s1x = 0.f, s1y = 0.f, s1z = 0.f;   // sum target
        float s2x = 0.f, s2y = 0.f, s2z = 0.f;   // sum output
        float tt  = 0.f;                         // sum target·target
        float c00 = 0.f, c01 = 0.f, c02 = 0.f;   // sum t_a * o_b
        float c10 = 0.f, c11 = 0.f, c12 = 0.f;
        float c20 = 0.f, c21 = 0.f, c22 = 0.f;

        for (int j = lane; j < KPT; j += 32) {
            float ox = p_o[3 * j + 0], oy = p_o[3 * j + 1], oz = p_o[3 * j + 2];
            float tx = p_t[3 * j + 0], ty = p_t[3 * j + 1], tz = p_t[3 * j + 2];
            s2x += ox; s2y += oy; s2z += oz;
            s1x += tx; s1y += ty; s1z += tz;
            tt  += tx * tx + ty * ty + tz * tz;
            c00 += tx * ox; c01 += tx * oy; c02 += tx * oz;
            c10 += ty * ox; c11 += ty * oy; c12 += ty * oz;
            c20 += tz * ox; c21 += tz * oy; c22 += tz * oz;
        }

        s1x = warp_sum(s1x); s1y = warp_sum(s1y); s1z = warp_sum(s1z);
        s2x = warp_sum(s2x); s2y = warp_sum(s2y); s2z = warp_sum(s2z);
        tt  = warp_sum(tt);
        c00 = warp_sum(c00); c01 = warp_sum(c01); c02 = warp_sum(c02);
        c10 = warp_sum(c10); c11 = warp_sum(c11); c12 = warp_sum(c12);
        c20 = warp_sum(c20); c21 = warp_sum(c21); c22 = warp_sum(c22);

        if (lane == 0) {
            const float invK = 1.0f / (float)KPT;
            float m1x = s1x * invK, m1y = s1y * invK, m1z = s1z * invK;
            float m2x = s2x * invK, m2y = s2y * invK, m2z = s2z * invK;
            float* T = sh_task + w * 16;
            const float fK = (float)KPT;
            T[0] = c00 - fK * m1x * m2x;  T[1] = c01 - fK * m1x * m2y;  T[2] = c02 - fK * m1x * m2z;
            T[3] = c10 - fK * m1y * m2x;  T[4] = c11 - fK * m1y * m2y;  T[5] = c12 - fK * m1y * m2z;
            T[6] = c20 - fK * m1z * m2x;  T[7] = c21 - fK * m1z * m2y;  T[8] = c22 - fK * m1z * m2z;
            T[9]  = tt - fK * (m1x * m1x + m1y * m1y + m1z * m1z);
            T[10] = m1x; T[11] = m1y; T[12] = m1z;
            T[13] = m2x; T[14] = m2y; T[15] = m2z;
        }
    }
    __syncthreads();

    // ---------------- Phase B: batched 3x3 SVD (warp 0, lane-per-sample) ----
    if (w == 0 && lane < WPB) {
        int s2i = blockIdx.x * WPB + lane;
        if (s2i < n) {
            const float* T = sh_task + lane * 16;
            float k00 = T[0], k01 = T[1], k02 = T[2];
            float k10 = T[3], k11 = T[4], k12 = T[5];
            float k20 = T[6], k21 = T[7], k22 = T[8];
            float var1 = T[9];

            // B = K^T K (symmetric)
            float b00 = k00 * k00 + k10 * k10 + k20 * k20;
            float b01 = k00 * k01 + k10 * k11 + k20 * k21;
            float b02 = k00 * k02 + k10 * k12 + k20 * k22;
            float b11 = k01 * k01 + k11 * k11 + k21 * k21;
            float b12 = k01 * k02 + k11 * k12 + k21 * k22;
            float b22 = k02 * k02 + k12 * k12 + k22 * k22;

            float v00 = 1.f, v01 = 0.f, v02 = 0.f;
            float v10 = 0.f, v11 = 1.f, v12 = 0.f;
            float v20 = 0.f, v21 = 0.f, v22 = 1.f;

#pragma unroll
            for (int sweep = 0; sweep < 5; ++sweep) {
                jrot(b00, b11, b01, b02, b12, v00, v01, v10, v11, v20, v21);
                jrot(b00, b22, b02, b01, b12, v00, v02, v10, v12, v20, v22);
                jrot(b11, b22, b12, b01, b02, v01, v02, v11, v12, v21, v22);
            }

            // sort eigenpairs descending: columns of V
            if (b00 < b11) CSWAP(b00, b11, v00, v01, v10, v11, v20, v21);
            if (b00 < b22) CSWAP(b00, b22, v00, v02, v10, v12, v20, v22);
            if (b11 < b22) CSWAP(b11, b22, v01, v02, v11, v12, v21, v22);

            float s0 = sqrtf(fmaxf(b00, 0.f));
            float s1 = sqrtf(fmaxf(b11, 0.f));
            float s2 = sqrtf(fmaxf(b22, 0.f));

            // u0 = K v0 / s0 ; u1 = K v1 / s1
            float a0 = k00 * v00 + k01 * v10 + k02 * v20;
            float a1 = k10 * v00 + k11 * v10 + k12 * v20;
            float a2 = k20 * v00 + k21 * v10 + k22 * v20;
            float inv0 = 1.f / fmaxf(s0, 1e-30f);
            float u0x = a0 * inv0, u0y = a1 * inv0, u0z = a2 * inv0;

            float e0 = k00 * v01 + k01 * v11 + k02 * v21;
            float e1 = k10 * v01 + k11 * v11 + k12 * v21;
            float e2 = k20 * v01 + k21 * v11 + k22 * v21;
            float inv1 = 1.f / fmaxf(s1, 1e-30f);
            float u1x = e0 * inv1, u1y = e1 * inv1, u1z = e2 * inv1;

            // u2 from cross product (robust), sign matched to K v2
            float g0 = k00 * v02 + k01 * v12 + k02 * v22;
            float g1 = k10 * v02 + k11 * v12 + k12 * v22;
            float g2 = k20 * v02 + k21 * v12 + k22 * v22;
            float wx = u0y * u1z - u0z * u1y;
            float wy = u0z * u1x - u0x * u1z;
            float wz = u0x * u1y - u0y * u1x;
            float wn = rsqrtf(fmaxf(wx * wx + wy * wy + wz * wz, 1e-30f));
            wx *= wn; wy *= wn; wz *= wn;
            float sgn = (g0 * wx + g1 * wy + g2 * wz) >= 0.f ? 1.f : -1.f;
            float u2x = sgn * wx, u2y = sgn * wy, u2z = sgn * wz;

            // reflection fix: z = sign(det K) (== sign(det(U@Vh)) in reference)
            float detK = k00 * (k11 * k22 - k12 * k21)
                       - k01 * (k10 * k22 - k12 * k20)
                       + k02 * (k10 * k21 - k11 * k20);
            float z = (detK >= 0.f) ? 1.f : -1.f;

            float scale = (s0 + s1 + z * s2) / var1;

            // R = v0 u0^T + v1 u1^T + z v2 u2^T   (cols of V are v_i)
            float* Rm = sh_res + lane * 16;
            Rm[0] = v00 * u0x + v01 * u1x + z * v02 * u2x;
            Rm[1] = v00 * u0y + v01 * u1y + z * v02 * u2y;
            Rm[2] = v00 * u0z + v01 * u1z + z * v02 * u2z;
            Rm[3] = v10 * u0x + v11 * u1x + z * v12 * u2x;
            Rm[4] = v10 * u0y + v11 * u1y + z * v12 * u2y;
            Rm[5] = v10 * u0z + v11 * u1z + z * v12 * u2z;
            Rm[6] = v20 * u0x + v21 * u1x + z * v22 * u2x;
            Rm[7] = v20 * u0y + v21 * u1y + z * v22 * u2y;
            Rm[8] = v20 * u0z + v21 * u1z + z * v22 * u2z;
            Rm[9]  = scale;
            Rm[10] = T[10]; Rm[11] = T[11]; Rm[12] = T[12];
            Rm[13] = T[13]; Rm[14] = T[14]; Rm[15] = T[15];
        }
    }
    __syncthreads();

    // ---------------- Phase C: residual norms ----------------
    if (valid) {
        const float* Rm = sh_res + w * 16;
        float r00 = Rm[0], r01 = Rm[1], r02 = Rm[2];
        float r10 = Rm[3], r11 = Rm[4], r12 = Rm[5];
        float r20 = Rm[6], r21 = Rm[7], r22 = Rm[8];
        float sc  = Rm[9];
        float m1x = Rm[10], m1y = Rm[11], m1z = Rm[12];
        float m2x = Rm[13], m2y = Rm[14], m2z = Rm[15];

        float lsum = 0.f;
        for (int j = lane; j < KPT; j += 32) {
            float tx = p_t[3 * j + 0] - m1x;
            float ty = p_t[3 * j + 1] - m1y;
            float tz = p_t[3 * j + 2] - m1z;
            float ax = sc * (r00 * tx + r01 * ty + r02 * tz) + m2x;
            float ay = sc * (r10 * tx + r11 * ty + r12 * tz) + m2y;
            float az = sc * (r20 * tx + r21 * ty + r22 * tz) + m2z;
            float dx = p_o[3 * j + 0] - ax;
            float dy = p_o[3 * j + 1] - ay;
            float dz = p_o[3 * j + 2] - az;
            lsum += sqrtf(dx * dx + dy * dy + dz * dz);
        }
        lsum = warp_sum(lsum);
        if (lane == 0) atomicAdd(&g_acc, (double)lsum);
    }
}

extern "C" void kernel_launch(void* const* d_in, const int* in_sizes, int n_in,
                              void* d_out, int out_size)
{
    const float* g_output = (const float*)d_in[0];
    const float* g_target = (const float*)d_in[1];
    int n = in_sizes[0] / PTS3;

    size_t shbytes = (size_t)(2 * WPB * PTS3 + 2 * WPB * 16) * sizeof(float);
    cudaFuncSetAttribute(k_pa, cudaFuncAttributeMaxDynamicSharedMemorySize, (int)shbytes);

    k_zero<<<1, 1>>>();
    int blocks = (n + WPB - 1) / WPB;
    k_pa<<<blocks, WPB * 32, shbytes>>>(g_output, g_target, n);
    double inv_cnt = 1.0 / ((double)n * (double)KPT);
    k_final<<<1, 1>>>((float*)d_out, inv_cnt);
}

// round 2
// speedup vs baseline: 1.2917x; 1.2917x over previous
#include <cuda_runtime.h>
#include <math.h>

#define WPB   16          // warps (= samples) per block
#define KPT   133
#define PTS3  399
#define MAXBLK 8192

__device__ double g_part[MAXBLK];

__device__ __forceinline__ float warp_sum(float v) {
#pragma unroll
    for (int o = 16; o > 0; o >>= 1) v += __shfl_xor_sync(0xffffffffu, v, o);
    return v;
}

// One cyclic-Jacobi rotation in the (p,q) plane of symmetric B, with the single
// off-plane element pair (bkp,bkq) and the V columns (p,q) updated.
__device__ __forceinline__ void jrot(float& app, float& aqq, float& apq,
                                     float& bkp, float& bkq,
                                     float& vp0, float& vq0,
                                     float& vp1, float& vq1,
                                     float& vp2, float& vq2)
{
    float a = apq;
    if (fabsf(a) > 1e-30f) {
        float theta = 0.5f * (aqq - app) / a;
        float t = copysignf(1.f, theta) / (fabsf(theta) + sqrtf(theta * theta + 1.f));
        float c = rsqrtf(t * t + 1.f);
        float s = t * c;
        app -= t * a;
        aqq += t * a;
        apq = 0.f;
        float t0 = bkp, t1 = bkq;
        bkp = c * t0 - s * t1;  bkq = s * t0 + c * t1;
        t0 = vp0; t1 = vq0; vp0 = c * t0 - s * t1; vq0 = s * t0 + c * t1;
        t0 = vp1; t1 = vq1; vp1 = c * t0 - s * t1; vq1 = s * t0 + c * t1;
        t0 = vp2; t1 = vq2; vp2 = c * t0 - s * t1; vq2 = s * t0 + c * t1;
    }
}

#define CSWAP(la, lb, x0, x1, y0, y1, z0, z1) \
    { float _t; _t = la; la = lb; lb = _t; _t = x0; x0 = x1; x1 = _t; \
      _t = y0; y0 = y1; y1 = _t; _t = z0; z0 = z1; z1 = _t; }

__global__ void k_pa(const float* __restrict__ g_outp,
                     const float* __restrict__ g_tgtp, int n)
{
    extern __shared__ float dyn[];
    float* sh_o    = dyn;                        // [WPB][PTS3]
    float* sh_t    = dyn + WPB * PTS3;           // [WPB][PTS3]
    float* sh_task = dyn + 2 * WPB * PTS3;       // [WPB][16]
    float* sh_res  = sh_task + WPB * 16;         // [WPB][16]
    float* sh_warp = sh_res + WPB * 16;          // [WPB] per-warp partial sums

    const int tid    = threadIdx.x;
    const int w      = tid >> 5;
    const int lane   = tid & 31;
    const int sample = blockIdx.x * WPB + w;
    const bool valid = (sample < n);

    // ---------------- Stage: block-cooperative float4 loads ----------------
    {
        const size_t base = (size_t)blockIdx.x * WPB * PTS3;      // 16B-aligned
        int rem   = n - blockIdx.x * WPB;
        int elems = (rem >= WPB ? WPB : rem) * PTS3;
        int nvec  = elems >> 2;
        const float4* go4 = (const float4*)(g_outp + base);
        const float4* gt4 = (const float4*)(g_tgtp + base);
        float4* so4 = (float4*)sh_o;
        float4* st4 = (float4*)sh_t;
        for (int i = tid; i < nvec; i += WPB * 32) {
            so4[i] = go4[i];
            st4[i] = gt4[i];
        }
        for (int i = (nvec << 2) + tid; i < elems; i += WPB * 32) {
            sh_o[i] = g_outp[base + i];
            sh_t[i] = g_tgtp[base + i];
        }
    }
    __syncthreads();

    float* p_o = sh_o + w * PTS3;
    float* p_t = sh_t + w * PTS3;

    // ---------------- Phase A: per-sample reductions ----------------
    if (valid) {
        float s1x = 0.f, s1y = 0.f, s1z = 0.f;   // sum target
        float s2x = 0.f, s2y = 0.f, s2z = 0.f;   // sum output
        float tt  = 0.f;                         // sum target·target
        float c00 = 0.f, c01 = 0.f, c02 = 0.f;   // sum t_a * o_b
        float c10 = 0.f, c11 = 0.f, c12 = 0.f;
        float c20 = 0.f, c21 = 0.f, c22 = 0.f;

        for (int j = lane; j < KPT; j += 32) {
            float ox = p_o[3 * j + 0], oy = p_o[3 * j + 1], oz = p_o[3 * j + 2];
            float tx = p_t[3 * j + 0], ty = p_t[3 * j + 1], tz = p_t[3 * j + 2];
            s2x += ox; s2y += oy; s2z += oz;
            s1x += tx; s1y += ty; s1z += tz;
            tt  += tx * tx + ty * ty + tz * tz;
            c00 += tx * ox; c01 += tx * oy; c02 += tx * oz;
            c10 += ty * ox; c11 += ty * oy; c12 += ty * oz;
            c20 += tz * ox; c21 += tz * oy; c22 += tz * oz;
        }

        s1x = warp_sum(s1x); s1y = warp_sum(s1y); s1z = warp_sum(s1z);
        s2x = warp_sum(s2x); s2y = warp_sum(s2y); s2z = warp_sum(s2z);
        tt  = warp_sum(tt);
        c00 = warp_sum(c00); c01 = warp_sum(c01); c02 = warp_sum(c02);
        c10 = warp_sum(c10); c11 = warp_sum(c11); c12 = warp_sum(c12);
        c20 = warp_sum(c20); c21 = warp_sum(c21); c22 = warp_sum(c22);

        if (lane == 0) {
            const float invK = 1.0f / (float)KPT;
            float m1x = s1x * invK, m1y = s1y * invK, m1z = s1z * invK;
            float m2x = s2x * invK, m2y = s2y * invK, m2z = s2z * invK;
            float* T = sh_task + w * 16;
            const float fK = (float)KPT;
            T[0] = c00 - fK * m1x * m2x;  T[1] = c01 - fK * m1x * m2y;  T[2] = c02 - fK * m1x * m2z;
            T[3] = c10 - fK * m1y * m2x;  T[4] = c11 - fK * m1y * m2y;  T[5] = c12 - fK * m1y * m2z;
            T[6] = c20 - fK * m1z * m2x;  T[7] = c21 - fK * m1z * m2y;  T[8] = c22 - fK * m1z * m2z;
            T[9]  = tt - fK * (m1x * m1x + m1y * m1y + m1z * m1z);
            T[10] = m1x; T[11] = m1y; T[12] = m1z;
            T[13] = m2x; T[14] = m2y; T[15] = m2z;
        }
    }
    __syncthreads();

    // ---------------- Phase B: batched 3x3 SVD (warp 0, lane-per-sample) ----
    if (w == 0 && lane < WPB) {
        int s2i = blockIdx.x * WPB + lane;
        if (s2i < n) {
            const float* T = sh_task + lane * 16;
            float k00 = T[0], k01 = T[1], k02 = T[2];
            float k10 = T[3], k11 = T[4], k12 = T[5];
            float k20 = T[6], k21 = T[7], k22 = T[8];
            float var1 = T[9];

            // B = K^T K (symmetric)
            float b00 = k00 * k00 + k10 * k10 + k20 * k20;
            float b01 = k00 * k01 + k10 * k11 + k20 * k21;
            float b02 = k00 * k02 + k10 * k12 + k20 * k22;
            float b11 = k01 * k01 + k11 * k11 + k21 * k21;
            float b12 = k01 * k02 + k11 * k12 + k21 * k22;
            float b22 = k02 * k02 + k12 * k12 + k22 * k22;

            float v00 = 1.f, v01 = 0.f, v02 = 0.f;
            float v10 = 0.f, v11 = 1.f, v12 = 0.f;
            float v20 = 0.f, v21 = 0.f, v22 = 1.f;

#pragma unroll
            for (int sweep = 0; sweep < 5; ++sweep) {
                jrot(b00, b11, b01, b02, b12, v00, v01, v10, v11, v20, v21);
                jrot(b00, b22, b02, b01, b12, v00, v02, v10, v12, v20, v22);
                jrot(b11, b22, b12, b01, b02, v01, v02, v11, v12, v21, v22);
            }

            // sort eigenpairs descending (columns of V)
            if (b00 < b11) CSWAP(b00, b11, v00, v01, v10, v11, v20, v21);
            if (b00 < b22) CSWAP(b00, b22, v00, v02, v10, v12, v20, v22);
            if (b11 < b22) CSWAP(b11, b22, v01, v02, v11, v12, v21, v22);

            float s0 = sqrtf(fmaxf(b00, 0.f));
            float s1 = sqrtf(fmaxf(b11, 0.f));
            float s2 = sqrtf(fmaxf(b22, 0.f));

            // u0 = K v0 / s0 ; u1 = K v1 / s1
            float a0 = k00 * v00 + k01 * v10 + k02 * v20;
            float a1 = k10 * v00 + k11 * v10 + k12 * v20;
            float a2 = k20 * v00 + k21 * v10 + k22 * v20;
            float inv0 = 1.f / fmaxf(s0, 1e-30f);
            float u0x = a0 * inv0, u0y = a1 * inv0, u0z = a2 * inv0;

            float e0 = k00 * v01 + k01 * v11 + k02 * v21;
            float e1 = k10 * v01 + k11 * v11 + k12 * v21;
            float e2 = k20 * v01 + k21 * v11 + k22 * v21;
            float inv1 = 1.f / fmaxf(s1, 1e-30f);
            float u1x = e0 * inv1, u1y = e1 * inv1, u1z = e2 * inv1;

            // u2 from cross product (robust), sign matched to K v2
            float g0 = k00 * v02 + k01 * v12 + k02 * v22;
            float g1 = k10 * v02 + k11 * v12 + k12 * v22;
            float g2 = k20 * v02 + k21 * v12 + k22 * v22;
            float wx = u0y * u1z - u0z * u1y;
            float wy = u0z * u1x - u0x * u1z;
            float wz = u0x * u1y - u0y * u1x;
            float wn = rsqrtf(fmaxf(wx * wx + wy * wy + wz * wz, 1e-30f));
            wx *= wn; wy *= wn; wz *= wn;
            float sgn = (g0 * wx + g1 * wy + g2 * wz) >= 0.f ? 1.f : -1.f;
            float u2x = sgn * wx, u2y = sgn * wy, u2z = sgn * wz;

            // reflection fix: z = sign(det K)
            float detK = k00 * (k11 * k22 - k12 * k21)
                       - k01 * (k10 * k22 - k12 * k20)
                       + k02 * (k10 * k21 - k11 * k20);
            float z = (detK >= 0.f) ? 1.f : -1.f;

            float scale = (s0 + s1 + z * s2) / var1;

            // R = v0 u0^T + v1 u1^T + z v2 u2^T — scale folded in
            float* Rm = sh_res + lane * 16;
            Rm[0] = scale * (v00 * u0x + v01 * u1x + z * v02 * u2x);
            Rm[1] = scale * (v00 * u0y + v01 * u1y + z * v02 * u2y);
            Rm[2] = scale * (v00 * u0z + v01 * u1z + z * v02 * u2z);
            Rm[3] = scale * (v10 * u0x + v11 * u1x + z * v12 * u2x);
            Rm[4] = scale * (v10 * u0y + v11 * u1y + z * v12 * u2y);
            Rm[5] = scale * (v10 * u0z + v11 * u1z + z * v12 * u2z);
            Rm[6] = scale * (v20 * u0x + v21 * u1x + z * v22 * u2x);
            Rm[7] = scale * (v20 * u0y + v21 * u1y + z * v22 * u2y);
            Rm[8] = scale * (v20 * u0z + v21 * u1z + z * v22 * u2z);
            Rm[10] = T[10]; Rm[11] = T[11]; Rm[12] = T[12];
            Rm[13] = T[13]; Rm[14] = T[14]; Rm[15] = T[15];
        }
    }
    __syncthreads();

    // ---------------- Phase C: residual norms ----------------
    {
        float lsum = 0.f;
        if (valid) {
            const float* Rm = sh_res + w * 16;
            float r00 = Rm[0], r01 = Rm[1], r02 = Rm[2];
            float r10 = Rm[3], r11 = Rm[4], r12 = Rm[5];
            float r20 = Rm[6], r21 = Rm[7], r22 = Rm[8];
            float m1x = Rm[10], m1y = Rm[11], m1z = Rm[12];
            float m2x = Rm[13], m2y = Rm[14], m2z = Rm[15];

            for (int j = lane; j < KPT; j += 32) {
                float tx = p_t[3 * j + 0] - m1x;
                float ty = p_t[3 * j + 1] - m1y;
                float tz = p_t[3 * j + 2] - m1z;
                float ax = r00 * tx + r01 * ty + r02 * tz + m2x;
                float ay = r10 * tx + r11 * ty + r12 * tz + m2y;
                float az = r20 * tx + r21 * ty + r22 * tz + m2z;
                float dx = p_o[3 * j + 0] - ax;
                float dy = p_o[3 * j + 1] - ay;
                float dz = p_o[3 * j + 2] - az;
                float d2 = fmaxf(dx * dx + dy * dy + dz * dz, 1e-30f);
                lsum += d2 * rsqrtf(d2);          // MUFU-based sqrt
            }
            lsum = warp_sum(lsum);
        }
        if (lane == 0) sh_warp[w] = lsum;
    }
    __syncthreads();

    // per-block reduce: 16 warp partials -> one double, no atomics
    if (tid < 32) {
        float v = (lane < WPB) ? sh_warp[lane] : 0.f;
#pragma unroll
        for (int o = 8; o > 0; o >>= 1) v += __shfl_xor_sync(0xffffffffu, v, o);
        if (lane == 0) g_part[blockIdx.x] = (double)v;
    }
}

__global__ void k_reduce(float* __restrict__ out, int nblocks, double inv_cnt)
{
    __shared__ double sh[32];
    double s = 0.0;
    for (int i = threadIdx.x; i < nblocks; i += blockDim.x) s += g_part[i];
#pragma unroll
    for (int o = 16; o > 0; o >>= 1) s += __shfl_xor_sync(0xffffffffu, s, o);
    int w = threadIdx.x >> 5, lane = threadIdx.x & 31;
    if (lane == 0) sh[w] = s;
    __syncthreads();
    if (threadIdx.x < 32) {
        int nw = blockDim.x >> 5;
        double v = (threadIdx.x < nw) ? sh[threadIdx.x] : 0.0;
#pragma unroll
        for (int o = 16; o > 0; o >>= 1) v += __shfl_xor_sync(0xffffffffu, v, o);
        if (threadIdx.x == 0) out[0] = (float)(v * inv_cnt);
    }
}

extern "C" void kernel_launch(void* const* d_in, const int* in_sizes, int n_in,
                              void* d_out, int out_size)
{
    const float* g_output = (const float*)d_in[0];
    const float* g_target = (const float*)d_in[1];
    int n = in_sizes[0] / PTS3;

    size_t shbytes = (size_t)(2 * WPB * PTS3 + 2 * WPB * 16 + WPB) * sizeof(float);
    cudaFuncSetAttribute(k_pa, cudaFuncAttributeMaxDynamicSharedMemorySize, (int)shbytes);

    int blocks = (n + WPB - 1) / WPB;
    k_pa<<<blocks, WPB * 32, shbytes>>>(g_output, g_target, n);
    double inv_cnt = 1.0 / ((double)n * (double)KPT);
    k_reduce<<<1, 512>>>((float*)d_out, blocks, inv_cnt);
}

// round 3
// speedup vs baseline: 1.8235x; 1.4118x over previous
#include <cuda_runtime.h>
#include <math.h>

#define WPB   8           // warps (= samples) per block
#define KPT   133
#define PTS3  399
#define MAXBLK 8192
#define RED1  32          // stage-1 reduction blocks

__device__ double g_part[MAXBLK];
__device__ double g_part2[RED1];

__device__ __forceinline__ float warp_sum(float v) {
#pragma unroll
    for (int o = 16; o > 0; o >>= 1) v += __shfl_xor_sync(0xffffffffu, v, o);
    return v;
}

// One cyclic-Jacobi rotation in the (p,q) plane of symmetric B, with the single
// off-plane element pair (bkp,bkq) and the V columns (p,q) updated.
__device__ __forceinline__ void jrot(float& app, float& aqq, float& apq,
                                     float& bkp, float& bkq,
                                     float& vp0, float& vq0,
                                     float& vp1, float& vq1,
                                     float& vp2, float& vq2)
{
    float a = apq;
    if (fabsf(a) > 1e-30f) {
        float theta = 0.5f * (aqq - app) / a;
        float t = copysignf(1.f, theta) / (fabsf(theta) + sqrtf(theta * theta + 1.f));
        float c = rsqrtf(t * t + 1.f);
        float s = t * c;
        app -= t * a;
        aqq += t * a;
        apq = 0.f;
        float t0 = bkp, t1 = bkq;
        bkp = c * t0 - s * t1;  bkq = s * t0 + c * t1;
        t0 = vp0; t1 = vq0; vp0 = c * t0 - s * t1; vq0 = s * t0 + c * t1;
        t0 = vp1; t1 = vq1; vp1 = c * t0 - s * t1; vq1 = s * t0 + c * t1;
        t0 = vp2; t1 = vq2; vp2 = c * t0 - s * t1; vq2 = s * t0 + c * t1;
    }
}

#define CSWAP(la, lb, x0, x1, y0, y1, z0, z1) \
    { float _t; _t = la; la = lb; lb = _t; _t = x0; x0 = x1; x1 = _t; \
      _t = y0; y0 = y1; y1 = _t; _t = z0; z0 = z1; z1 = _t; }

__global__ void __launch_bounds__(WPB * 32, 6)
k_pa(const float* __restrict__ g_outp, const float* __restrict__ g_tgtp, int n)
{
    extern __shared__ float dyn[];
    float* sh_o    = dyn;                        // [WPB][PTS3]
    float* sh_t    = dyn + WPB * PTS3;           // [WPB][PTS3]
    float* sh_task = dyn + 2 * WPB * PTS3;       // [WPB][16]
    float* sh_res  = sh_task + WPB * 16;         // [WPB][16]
    float* sh_warp = sh_res + WPB * 16;          // [WPB]

    const int tid    = threadIdx.x;
    const int w      = tid >> 5;
    const int lane   = tid & 31;
    const int sample = blockIdx.x * WPB + w;
    const bool valid = (sample < n);

    // ---------------- Stage: block-cooperative float4 loads ----------------
    {
        const size_t base = (size_t)blockIdx.x * WPB * PTS3;      // 16B-aligned
        int rem   = n - blockIdx.x * WPB;
        int elems = (rem >= WPB ? WPB : rem) * PTS3;
        int nvec  = elems >> 2;
        const float4* go4 = (const float4*)(g_outp + base);
        const float4* gt4 = (const float4*)(g_tgtp + base);
        float4* so4 = (float4*)sh_o;
        float4* st4 = (float4*)sh_t;
        for (int i = tid; i < nvec; i += WPB * 32) {
            so4[i] = go4[i];
            st4[i] = gt4[i];
        }
        for (int i = (nvec << 2) + tid; i < elems; i += WPB * 32) {
            sh_o[i] = g_outp[base + i];
            sh_t[i] = g_tgtp[base + i];
        }
    }
    __syncthreads();

    float* p_o = sh_o + w * PTS3;
    float* p_t = sh_t + w * PTS3;

    // ---------------- Phase A: per-sample reductions ----------------
    if (valid) {
        float s1x = 0.f, s1y = 0.f, s1z = 0.f;
        float s2x = 0.f, s2y = 0.f, s2z = 0.f;
        float tt  = 0.f;
        float c00 = 0.f, c01 = 0.f, c02 = 0.f;
        float c10 = 0.f, c11 = 0.f, c12 = 0.f;
        float c20 = 0.f, c21 = 0.f, c22 = 0.f;

        for (int j = lane; j < KPT; j += 32) {
            float ox = p_o[3 * j + 0], oy = p_o[3 * j + 1], oz = p_o[3 * j + 2];
            float tx = p_t[3 * j + 0], ty = p_t[3 * j + 1], tz = p_t[3 * j + 2];
            s2x += ox; s2y += oy; s2z += oz;
            s1x += tx; s1y += ty; s1z += tz;
            tt  += tx * tx + ty * ty + tz * tz;
            c00 += tx * ox; c01 += tx * oy; c02 += tx * oz;
            c10 += ty * ox; c11 += ty * oy; c12 += ty * oz;
            c20 += tz * ox; c21 += tz * oy; c22 += tz * oz;
        }

        s1x = warp_sum(s1x); s1y = warp_sum(s1y); s1z = warp_sum(s1z);
        s2x = warp_sum(s2x); s2y = warp_sum(s2y); s2z = warp_sum(s2z);
        tt  = warp_sum(tt);
        c00 = warp_sum(c00); c01 = warp_sum(c01); c02 = warp_sum(c02);
        c10 = warp_sum(c10); c11 = warp_sum(c11); c12 = warp_sum(c12);
        c20 = warp_sum(c20); c21 = warp_sum(c21); c22 = warp_sum(c22);

        if (lane == 0) {
            const float invK = 1.0f / (float)KPT;
            float m1x = s1x * invK, m1y = s1y * invK, m1z = s1z * invK;
            float m2x = s2x * invK, m2y = s2y * invK, m2z = s2z * invK;
            float* T = sh_task + w * 16;
            const float fK = (float)KPT;
            T[0] = c00 - fK * m1x * m2x;  T[1] = c01 - fK * m1x * m2y;  T[2] = c02 - fK * m1x * m2z;
            T[3] = c10 - fK * m1y * m2x;  T[4] = c11 - fK * m1y * m2y;  T[5] = c12 - fK * m1y * m2z;
            T[6] = c20 - fK * m1z * m2x;  T[7] = c21 - fK * m1z * m2y;  T[8] = c22 - fK * m1z * m2z;
            T[9]  = tt - fK * (m1x * m1x + m1y * m1y + m1z * m1z);
            T[10] = m1x; T[11] = m1y; T[12] = m1z;
            T[13] = m2x; T[14] = m2y; T[15] = m2z;
        }
    }
    __syncthreads();

    // ---------------- Phase B: batched 3x3 SVD (warp 0, lane-per-sample) ----
    if (w == 0 && lane < WPB) {
        int s2i = blockIdx.x * WPB + lane;
        if (s2i < n) {
            const float* T = sh_task + lane * 16;
            float k00 = T[0], k01 = T[1], k02 = T[2];
            float k10 = T[3], k11 = T[4], k12 = T[5];
            float k20 = T[6], k21 = T[7], k22 = T[8];
            float var1 = T[9];

            float b00 = k00 * k00 + k10 * k10 + k20 * k20;
            float b01 = k00 * k01 + k10 * k11 + k20 * k21;
            float b02 = k00 * k02 + k10 * k12 + k20 * k22;
            float b11 = k01 * k01 + k11 * k11 + k21 * k21;
            float b12 = k01 * k02 + k11 * k12 + k21 * k22;
            float b22 = k02 * k02 + k12 * k12 + k22 * k22;

            float v00 = 1.f, v01 = 0.f, v02 = 0.f;
            float v10 = 0.f, v11 = 1.f, v12 = 0.f;
            float v20 = 0.f, v21 = 0.f, v22 = 1.f;

#pragma unroll
            for (int sweep = 0; sweep < 5; ++sweep) {
                jrot(b00, b11, b01, b02, b12, v00, v01, v10, v11, v20, v21);
                jrot(b00, b22, b02, b01, b12, v00, v02, v10, v12, v20, v22);
                jrot(b11, b22, b12, b01, b02, v01, v02, v11, v12, v21, v22);
            }

            if (b00 < b11) CSWAP(b00, b11, v00, v01, v10, v11, v20, v21);
            if (b00 < b22) CSWAP(b00, b22, v00, v02, v10, v12, v20, v22);
            if (b11 < b22) CSWAP(b11, b22, v01, v02, v11, v12, v21, v22);

            float s0 = sqrtf(fmaxf(b00, 0.f));
            float s1 = sqrtf(fmaxf(b11, 0.f));
            float s2 = sqrtf(fmaxf(b22, 0.f));

            float a0 = k00 * v00 + k01 * v10 + k02 * v20;
            float a1 = k10 * v00 + k11 * v10 + k12 * v20;
            float a2 = k20 * v00 + k21 * v10 + k22 * v20;
            float inv0 = 1.f / fmaxf(s0, 1e-30f);
            float u0x = a0 * inv0, u0y = a1 * inv0, u0z = a2 * inv0;

            float e0 = k00 * v01 + k01 * v11 + k02 * v21;
            float e1 = k10 * v01 + k11 * v11 + k12 * v21;
            float e2 = k20 * v01 + k21 * v11 + k22 * v21;
            float inv1 = 1.f / fmaxf(s1, 1e-30f);
            float u1x = e0 * inv1, u1y = e1 * inv1, u1z = e2 * inv1;

            float g0 = k00 * v02 + k01 * v12 + k02 * v22;
            float g1 = k10 * v02 + k11 * v12 + k12 * v22;
            float g2 = k20 * v02 + k21 * v12 + k22 * v22;
            float wx = u0y * u1z - u0z * u1y;
            float wy = u0z * u1x - u0x * u1z;
            float wz = u0x * u1y - u0y * u1x;
            float wn = rsqrtf(fmaxf(wx * wx + wy * wy + wz * wz, 1e-30f));
            wx *= wn; wy *= wn; wz *= wn;
            float sgn = (g0 * wx + g1 * wy + g2 * wz) >= 0.f ? 1.f : -1.f;
            float u2x = sgn * wx, u2y = sgn * wy, u2z = sgn * wz;

            float detK = k00 * (k11 * k22 - k12 * k21)
                       - k01 * (k10 * k22 - k12 * k20)
                       + k02 * (k10 * k21 - k11 * k20);
            float z = (detK >= 0.f) ? 1.f : -1.f;

            float scale = (s0 + s1 + z * s2) / var1;

            float* Rm = sh_res + lane * 16;
            Rm[0] = scale * (v00 * u0x + v01 * u1x + z * v02 * u2x);
            Rm[1] = scale * (v00 * u0y + v01 * u1y + z * v02 * u2y);
            Rm[2] = scale * (v00 * u0z + v01 * u1z + z * v02 * u2z);
            Rm[3] = scale * (v10 * u0x + v11 * u1x + z * v12 * u2x);
            Rm[4] = scale * (v10 * u0y + v11 * u1y + z * v12 * u2y);
            Rm[5] = scale * (v10 * u0z + v11 * u1z + z * v12 * u2z);
            Rm[6] = scale * (v20 * u0x + v21 * u1x + z * v22 * u2x);
            Rm[7] = scale * (v20 * u0y + v21 * u1y + z * v22 * u2y);
            Rm[8] = scale * (v20 * u0z + v21 * u1z + z * v22 * u2z);
            Rm[10] = T[10]; Rm[11] = T[11]; Rm[12] = T[12];
            Rm[13] = T[13]; Rm[14] = T[14]; Rm[15] = T[15];
        }
    }
    __syncthreads();

    // ---------------- Phase C: residual norms ----------------
    {
        float lsum = 0.f;
        if (valid) {
            const float* Rm = sh_res + w * 16;
            float r00 = Rm[0], r01 = Rm[1], r02 = Rm[2];
            float r10 = Rm[3], r11 = Rm[4], r12 = Rm[5];
            float r20 = Rm[6], r21 = Rm[7], r22 = Rm[8];
            float m1x = Rm[10], m1y = Rm[11], m1z = Rm[12];
            float m2x = Rm[13], m2y = Rm[14], m2z = Rm[15];

            for (int j = lane; j < KPT; j += 32) {
                float tx = p_t[3 * j + 0] - m1x;
                float ty = p_t[3 * j + 1] - m1y;
                float tz = p_t[3 * j + 2] - m1z;
                float ax = r00 * tx + r01 * ty + r02 * tz + m2x;
                float ay = r10 * tx + r11 * ty + r12 * tz + m2y;
                float az = r20 * tx + r21 * ty + r22 * tz + m2z;
                float dx = p_o[3 * j + 0] - ax;
                float dy = p_o[3 * j + 1] - ay;
                float dz = p_o[3 * j + 2] - az;
                float d2 = fmaxf(dx * dx + dy * dy + dz * dz, 1e-30f);
                lsum += d2 * rsqrtf(d2);
            }
            lsum = warp_sum(lsum);
        }
        if (lane == 0) sh_warp[w] = lsum;
    }
    __syncthreads();

    if (tid < 32) {
        float v = (lane < WPB) ? sh_warp[lane] : 0.f;
#pragma unroll
        for (int o = 8; o > 0; o >>= 1) v += __shfl_xor_sync(0xffffffffu, v, o);
        if (lane == 0) g_part[blockIdx.x] = (double)v;
    }
}

// stage 1: RED1 blocks each sum a contiguous slab of g_part
__global__ void k_reduce1(int nblocks)
{
    __shared__ double sh[8];
    int per = (nblocks + RED1 - 1) / RED1;
    int lo  = blockIdx.x * per;
    int hi  = min(lo + per, nblocks);
    double s = 0.0;
    for (int i = lo + threadIdx.x; i < hi; i += blockDim.x) s += g_part[i];
#pragma unroll
    for (int o = 16; o > 0; o >>= 1) s += __shfl_xor_sync(0xffffffffu, s, o);
    int wi = threadIdx.x >> 5, lane = threadIdx.x & 31;
    if (lane == 0) sh[wi] = s;
    __syncthreads();
    if (threadIdx.x < 32) {
        int nw = blockDim.x >> 5;
        double v = (threadIdx.x < nw) ? sh[threadIdx.x] : 0.0;
#pragma unroll
        for (int o = 4; o > 0; o >>= 1) v += __shfl_xor_sync(0xffffffffu, v, o);
        if (threadIdx.x == 0) g_part2[blockIdx.x] = v;
    }
}

// stage 2: one warp sums RED1 values and writes the scalar
__global__ void k_reduce2(float* __restrict__ out, double inv_cnt)
{
    double v = (threadIdx.x < RED1) ? g_part2[threadIdx.x] : 0.0;
#pragma unroll
    for (int o = 16; o > 0; o >>= 1) v += __shfl_xor_sync(0xffffffffu, v, o);
    if (threadIdx.x == 0) out[0] = (float)(v * inv_cnt);
}

extern "C" void kernel_launch(void* const* d_in, const int* in_sizes, int n_in,
                              void* d_out, int out_size)
{
    const float* g_output = (const float*)d_in[0];
    const float* g_target = (const float*)d_in[1];
    int n = in_sizes[0] / PTS3;

    size_t shbytes = (size_t)(2 * WPB * PTS3 + 2 * WPB * 16 + WPB) * sizeof(float);
    cudaFuncSetAttribute(k_pa, cudaFuncAttributeMaxDynamicSharedMemorySize, (int)shbytes);

    int blocks = (n + WPB - 1) / WPB;
    k_pa<<<blocks, WPB * 32, shbytes>>>(g_output, g_target, n);
    k_reduce1<<<RED1, 256>>>(blocks);
    double inv_cnt = 1.0 / ((double)n * (double)KPT);
    k_reduce2<<<1, 32>>>((float*)d_out, inv_cnt);
}

// round 4
// speedup vs baseline: 2.1612x; 1.1852x over previous
#include <cuda_runtime.h>
#include <math.h>

#define KPT   133
#define PTS3  399
#define SPB   8            // samples per block (4 warps x 2 halves)
#define NPART (8192 * 4)
#define RED1  32

__device__ double g_part[NPART];
__device__ double g_part2[RED1];

// butterfly over a 16-lane half-warp (offsets 8..1); halves stay independent
__device__ __forceinline__ float hsum16(float v) {
#pragma unroll
    for (int o = 8; o > 0; o >>= 1) v += __shfl_xor_sync(0xffffffffu, v, o);
    return v;
}

// sqrt(x) for x>=0 via MUFU rsqrt (avoids IEEE slow path)
__device__ __forceinline__ float fsqrt_fast(float x) {
    return x * rsqrtf(fmaxf(x, 1e-30f));
}

// branchless cyclic-Jacobi rotation in the (p,q) plane of symmetric B
__device__ __forceinline__ void jrot(float& app, float& aqq, float& apq,
                                     float& bkp, float& bkq,
                                     float& vp0, float& vq0,
                                     float& vp1, float& vq1,
                                     float& vp2, float& vq2)
{
    float a  = apq;
    float aa = copysignf(fmaxf(fabsf(a), 1e-30f), a + 1e-38f);
    float theta = __fdividef(0.5f * (aqq - app), aa);
    float th = fminf(fmaxf(theta, -1e8f), 1e8f);      // clamp: huge theta => ~identity rot
    float t = __fdividef(copysignf(1.f, th), fabsf(th) + fsqrt_fast(th * th + 1.f));
    float c = rsqrtf(t * t + 1.f);
    float s = t * c;
    app -= t * a;
    aqq += t * a;
    apq = 0.f;
    float t0 = bkp, t1 = bkq;
    bkp = c * t0 - s * t1;  bkq = s * t0 + c * t1;
    t0 = vp0; t1 = vq0; vp0 = c * t0 - s * t1; vq0 = s * t0 + c * t1;
    t0 = vp1; t1 = vq1; vp1 = c * t0 - s * t1; vq1 = s * t0 + c * t1;
    t0 = vp2; t1 = vq2; vp2 = c * t0 - s * t1; vq2 = s * t0 + c * t1;
}

#define CSWAP(la, lb, x0, x1, y0, y1, z0, z1) \
    { float _t; _t = la; la = lb; lb = _t; _t = x0; x0 = x1; x1 = _t; \
      _t = y0; y0 = y1; y1 = _t; _t = z0; z0 = z1; z1 = _t; }

__global__ void __launch_bounds__(128, 8)
k_pa(const float* __restrict__ g_outp, const float* __restrict__ g_tgtp, int n)
{
    const int tid  = threadIdx.x;
    const int warp = tid >> 5;
    const int lane = tid & 31;
    const int half = lane >> 4;          // 0 or 1: which sample of this warp
    const int l    = lane & 15;          // lane within the 16-lane sample group

    const int sample = blockIdx.x * SPB + warp * 2 + half;
    const bool valid = (sample < n);
    const int  s     = valid ? sample : 0;     // dummy-compute on sample 0 if OOB

    const float* __restrict__ po = g_outp + (size_t)s * PTS3;
    const float* __restrict__ pt = g_tgtp + (size_t)s * PTS3;

    // ---------------- Phase A: per-sample sums (16 lanes/sample) ----------------
    float s1x = 0.f, s1y = 0.f, s1z = 0.f;
    float s2x = 0.f, s2y = 0.f, s2z = 0.f;
    float tt  = 0.f;
    float c00 = 0.f, c01 = 0.f, c02 = 0.f;
    float c10 = 0.f, c11 = 0.f, c12 = 0.f;
    float c20 = 0.f, c21 = 0.f, c22 = 0.f;

    for (int j = l; j < KPT; j += 16) {
        float ox = po[3 * j + 0], oy = po[3 * j + 1], oz = po[3 * j + 2];
        float tx = pt[3 * j + 0], ty = pt[3 * j + 1], tz = pt[3 * j + 2];
        s2x += ox; s2y += oy; s2z += oz;
        s1x += tx; s1y += ty; s1z += tz;
        tt  += tx * tx + ty * ty + tz * tz;
        c00 += tx * ox; c01 += tx * oy; c02 += tx * oz;
        c10 += ty * ox; c11 += ty * oy; c12 += ty * oz;
        c20 += tz * ox; c21 += tz * oy; c22 += tz * oz;
    }

    s1x = hsum16(s1x); s1y = hsum16(s1y); s1z = hsum16(s1z);
    s2x = hsum16(s2x); s2y = hsum16(s2y); s2z = hsum16(s2z);
    tt  = hsum16(tt);
    c00 = hsum16(c00); c01 = hsum16(c01); c02 = hsum16(c02);
    c10 = hsum16(c10); c11 = hsum16(c11); c12 = hsum16(c12);
    c20 = hsum16(c20); c21 = hsum16(c21); c22 = hsum16(c22);

    // all 16 lanes of each half now hold the full sums for their sample
    const float invK = 1.0f / (float)KPT;
    float m1x = s1x * invK, m1y = s1y * invK, m1z = s1z * invK;
    float m2x = s2x * invK, m2y = s2y * invK, m2z = s2z * invK;

    float k00 = c00 - s1x * m2x, k01 = c01 - s1x * m2y, k02 = c02 - s1x * m2z;
    float k10 = c10 - s1y * m2x, k11 = c11 - s1y * m2y, k12 = c12 - s1y * m2z;
    float k20 = c20 - s1z * m2x, k21 = c21 - s1z * m2y, k22 = c22 - s1z * m2z;
    float var1 = tt - (s1x * m1x + s1y * m1y + s1z * m1z);

    // ---------------- Phase B: 3x3 SVD, redundant per half-warp ----------------
    float b00 = k00 * k00 + k10 * k10 + k20 * k20;
    float b01 = k00 * k01 + k10 * k11 + k20 * k21;
    float b02 = k00 * k02 + k10 * k12 + k20 * k22;
    float b11 = k01 * k01 + k11 * k11 + k21 * k21;
    float b12 = k01 * k02 + k11 * k12 + k21 * k22;
    float b22 = k02 * k02 + k12 * k12 + k22 * k22;

    float v00 = 1.f, v01 = 0.f, v02 = 0.f;
    float v10 = 0.f, v11 = 1.f, v12 = 0.f;
    float v20 = 0.f, v21 = 0.f, v22 = 1.f;

#pragma unroll
    for (int sweep = 0; sweep < 4; ++sweep) {
        jrot(b00, b11, b01, b02, b12, v00, v01, v10, v11, v20, v21);
        jrot(b00, b22, b02, b01, b12, v00, v02, v10, v12, v20, v22);
        jrot(b11, b22, b12, b01, b02, v01, v02, v11, v12, v21, v22);
    }

    if (b00 < b11) CSWAP(b00, b11, v00, v01, v10, v11, v20, v21);
    if (b00 < b22) CSWAP(b00, b22, v00, v02, v10, v12, v20, v22);
    if (b11 < b22) CSWAP(b11, b22, v01, v02, v11, v12, v21, v22);

    float s0 = fsqrt_fast(fmaxf(b00, 0.f));
    float s1 = fsqrt_fast(fmaxf(b11, 0.f));
    float s2 = fsqrt_fast(fmaxf(b22, 0.f));

    // u0 = K v0 / s0 ; u1 = K v1 / s1
    float a0 = k00 * v00 + k01 * v10 + k02 * v20;
    float a1 = k10 * v00 + k11 * v10 + k12 * v20;
    float a2 = k20 * v00 + k21 * v10 + k22 * v20;
    float inv0 = __fdividef(1.f, fmaxf(s0, 1e-30f));
    float u0x = a0 * inv0, u0y = a1 * inv0, u0z = a2 * inv0;

    float e0 = k00 * v01 + k01 * v11 + k02 * v21;
    float e1 = k10 * v01 + k11 * v11 + k12 * v21;
    float e2 = k20 * v01 + k21 * v11 + k22 * v21;
    float inv1 = __fdividef(1.f, fmaxf(s1, 1e-30f));
    float u1x = e0 * inv1, u1y = e1 * inv1, u1z = e2 * inv1;

    // u2 from cross product (robust), sign matched to K v2
    float g0 = k00 * v02 + k01 * v12 + k02 * v22;
    float g1 = k10 * v02 + k11 * v12 + k12 * v22;
    float g2 = k20 * v02 + k21 * v12 + k22 * v22;
    float wx = u0y * u1z - u0z * u1y;
    float wy = u0z * u1x - u0x * u1z;
    float wz = u0x * u1y - u0y * u1x;
    float wn = rsqrtf(fmaxf(wx * wx + wy * wy + wz * wz, 1e-30f));
    wx *= wn; wy *= wn; wz *= wn;
    float sgn = (g0 * wx + g1 * wy + g2 * wz) >= 0.f ? 1.f : -1.f;
    float u2x = sgn * wx, u2y = sgn * wy, u2z = sgn * wz;

    // reflection fix: z = sign(det K)
    float detK = k00 * (k11 * k22 - k12 * k21)
               - k01 * (k10 * k22 - k12 * k20)
               + k02 * (k10 * k21 - k11 * k20);
    float z = (detK >= 0.f) ? 1.f : -1.f;

    float scale = __fdividef(s0 + s1 + z * s2, var1);

    // R (scale folded): rows over target coords
    float r00 = scale * (v00 * u0x + v01 * u1x + z * v02 * u2x);
    float r01 = scale * (v00 * u0y + v01 * u1y + z * v02 * u2y);
    float r02 = scale * (v00 * u0z + v01 * u1z + z * v02 * u2z);
    float r10 = scale * (v10 * u0x + v11 * u1x + z * v12 * u2x);
    float r11 = scale * (v10 * u0y + v11 * u1y + z * v12 * u2y);
    float r12 = scale * (v10 * u0z + v11 * u1z + z * v12 * u2z);
    float r20 = scale * (v20 * u0x + v21 * u1x + z * v22 * u2x);
    float r21 = scale * (v20 * u0y + v21 * u1y + z * v22 * u2y);
    float r22 = scale * (v20 * u0z + v21 * u1z + z * v22 * u2z);

    // translation: trans = m2 - R*m1  (aligned = R*t + trans)
    float tr_x = m2x - (r00 * m1x + r01 * m1y + r02 * m1z);
    float tr_y = m2y - (r10 * m1x + r11 * m1y + r12 * m1z);
    float tr_z = m2z - (r20 * m1x + r21 * m1y + r22 * m1z);

    // ---------------- Phase C: residual norms (re-read, L1-hot) ----------------
    float lsum = 0.f;
    for (int j = l; j < KPT; j += 16) {
        float tx = pt[3 * j + 0], ty = pt[3 * j + 1], tz = pt[3 * j + 2];
        float ax = tr_x + r00 * tx + r01 * ty + r02 * tz;
        float ay = tr_y + r10 * tx + r11 * ty + r12 * tz;
        float az = tr_z + r20 * tx + r21 * ty + r22 * tz;
        float dx = po[3 * j + 0] - ax;
        float dy = po[3 * j + 1] - ay;
        float dz = po[3 * j + 2] - az;
        float d2 = fmaxf(dx * dx + dy * dy + dz * dz, 1e-30f);
        lsum += d2 * rsqrtf(d2);
    }
    lsum = hsum16(lsum);
    if (!valid) lsum = 0.f;

    // cross-half combine; lane 0 writes one double per warp
    float other = __shfl_xor_sync(0xffffffffu, lsum, 16);
    if (lane == 0)
        g_part[(size_t)blockIdx.x * 4 + warp] = (double)lsum + (double)other;
}

// stage 1: RED1 blocks each sum a contiguous slab of g_part
__global__ void k_reduce1(int nparts)
{
    __shared__ double sh[8];
    int per = (nparts + RED1 - 1) / RED1;
    int lo  = blockIdx.x * per;
    int hi  = min(lo + per, nparts);
    double s = 0.0;
    for (int i = lo + threadIdx.x; i < hi; i += blockDim.x) s += g_part[i];
#pragma unroll
    for (int o = 16; o > 0; o >>= 1) s += __shfl_xor_sync(0xffffffffu, s, o);
    int wi = threadIdx.x >> 5, lane = threadIdx.x & 31;
    if (lane == 0) sh[wi] = s;
    __syncthreads();
    if (threadIdx.x < 32) {
        int nw = blockDim.x >> 5;
        double v = (threadIdx.x < nw) ? sh[threadIdx.x] : 0.0;
#pragma unroll
        for (int o = 4; o > 0; o >>= 1) v += __shfl_xor_sync(0xffffffffu, v, o);
        if (threadIdx.x == 0) g_part2[blockIdx.x] = v;
    }
}

// stage 2: one warp sums RED1 values and writes the scalar
__global__ void k_reduce2(float* __restrict__ out, double inv_cnt)
{
    double v = (threadIdx.x < RED1) ? g_part2[threadIdx.x] : 0.0;
#pragma unroll
    for (int o = 16; o > 0; o >>= 1) v += __shfl_xor_sync(0xffffffffu, v, o);
    if (threadIdx.x == 0) out[0] = (float)(v * inv_cnt);
}

extern "C" void kernel_launch(void* const* d_in, const int* in_sizes, int n_in,
                              void* d_out, int out_size)
{
    const float* g_output = (const float*)d_in[0];
    const float* g_target = (const float*)d_in[1];
    int n = in_sizes[0] / PTS3;

    int blocks = (n + SPB - 1) / SPB;
    k_pa<<<blocks, 128>>>(g_output, g_target, n);
    k_reduce1<<<RED1, 256>>>(blocks * 4);
    double inv_cnt = 1.0 / ((double)n * (double)KPT);
    k_reduce2<<<1, 32>>>((float*)d_out, inv_cnt);
}

// round 5
// speedup vs baseline: 2.2393x; 1.0361x over previous
#include <cuda_runtime.h>
#include <math.h>

#define KPT   133
#define PTS3  399
#define SPW   4             // samples per warp (8 lanes each)
#define SPB   16            // samples per block (4 warps)
#define NPART (4096 * 4)
#define RED1  32

__device__ double g_part[NPART];
__device__ double g_part2[RED1];

// butterfly over an 8-lane group (offsets 4..1); groups stay independent
__device__ __forceinline__ float hsum8(float v) {
#pragma unroll
    for (int o = 4; o > 0; o >>= 1) v += __shfl_xor_sync(0xffffffffu, v, o);
    return v;
}

__device__ __forceinline__ float fsqrt_fast(float x) {
    return x * rsqrtf(fmaxf(x, 1e-30f));
}

// Exact minimal-angle Jacobi rotation, 2 MUFU, no divisions.
// Convention identical to Rutishauser: theta=(aqq-app)/(2a), t=sign/(|th|+sqrt(th^2+1)),
// expressed as tan(phi)=sh/ch with sh=2a*sign(d), ch=|d|+sqrt(d^2+4a^2), d=aqq-app.
__device__ __forceinline__ void jrot(float& app, float& aqq, float& apq,
                                     float& bkp, float& bkq,
                                     float& vp0, float& vq0,
                                     float& vp1, float& vq1,
                                     float& vp2, float& vq2)
{
    float a  = apq;
    float d  = aqq - app;
    float q2 = d * d + 4.f * a * a;
    float hyp = q2 * rsqrtf(fmaxf(q2, 1e-30f));          // sqrt(d^2+4a^2)
    float ch = fabsf(d) + hyp + 1e-15f;                  // >0
    float sh = 2.f * a * copysignf(1.f, d);
    float w  = rsqrtf(ch * ch + sh * sh);
    float c  = ch * w;
    float s  = sh * w;
    // closed-form eigenvalue update (== app - t*a / aqq + t*a)
    float cc = c * c, ss = s * s, cs2a = 2.f * c * s * a;
    float napp = cc * app + ss * aqq - cs2a;
    float naqq = ss * app + cc * aqq + cs2a;
    app = napp; aqq = naqq; apq = 0.f;
    float t0 = bkp, t1 = bkq;
    bkp = c * t0 - s * t1;  bkq = s * t0 + c * t1;
    t0 = vp0; t1 = vq0; vp0 = c * t0 - s * t1; vq0 = s * t0 + c * t1;
    t0 = vp1; t1 = vq1; vp1 = c * t0 - s * t1; vq1 = s * t0 + c * t1;
    t0 = vp2; t1 = vq2; vp2 = c * t0 - s * t1; vq2 = s * t0 + c * t1;
}

#define CSWAP(la, lb, x0, x1, y0, y1, z0, z1) \
    { float _t; _t = la; la = lb; lb = _t; _t = x0; x0 = x1; x1 = _t; \
      _t = y0; y0 = y1; y1 = _t; _t = z0; z0 = z1; z1 = _t; }

__global__ void __launch_bounds__(128, 8)
k_pa(const float* __restrict__ g_outp, const float* __restrict__ g_tgtp, int n)
{
    const int tid  = threadIdx.x;
    const int warp = tid >> 5;
    const int lane = tid & 31;
    const int grp  = lane >> 3;          // 0..3: sample index within warp
    const int q    = lane & 7;           // lane within the 8-lane sample group

    const int sample = blockIdx.x * SPB + warp * SPW + grp;
    const bool valid = (sample < n);
    const int  s     = valid ? sample : 0;

    const float* __restrict__ po = g_outp + (size_t)s * PTS3;
    const float* __restrict__ pt = g_tgtp + (size_t)s * PTS3;

    // ---------------- Phase A: per-sample sums (8 lanes/sample) ----------------
    float s1x = 0.f, s1y = 0.f, s1z = 0.f;
    float s2x = 0.f, s2y = 0.f, s2z = 0.f;
    float tt  = 0.f;
    float c00 = 0.f, c01 = 0.f, c02 = 0.f;
    float c10 = 0.f, c11 = 0.f, c12 = 0.f;
    float c20 = 0.f, c21 = 0.f, c22 = 0.f;

    for (int j = q; j < KPT; j += 8) {
        float ox = po[3 * j + 0], oy = po[3 * j + 1], oz = po[3 * j + 2];
        float tx = pt[3 * j + 0], ty = pt[3 * j + 1], tz = pt[3 * j + 2];
        s2x += ox; s2y += oy; s2z += oz;
        s1x += tx; s1y += ty; s1z += tz;
        tt  += tx * tx + ty * ty + tz * tz;
        c00 += tx * ox; c01 += tx * oy; c02 += tx * oz;
        c10 += ty * ox; c11 += ty * oy; c12 += ty * oz;
        c20 += tz * ox; c21 += tz * oy; c22 += tz * oz;
    }

    s1x = hsum8(s1x); s1y = hsum8(s1y); s1z = hsum8(s1z);
    s2x = hsum8(s2x); s2y = hsum8(s2y); s2z = hsum8(s2z);
    tt  = hsum8(tt);
    c00 = hsum8(c00); c01 = hsum8(c01); c02 = hsum8(c02);
    c10 = hsum8(c10); c11 = hsum8(c11); c12 = hsum8(c12);
    c20 = hsum8(c20); c21 = hsum8(c21); c22 = hsum8(c22);

    const float invK = 1.0f / (float)KPT;
    float m1x = s1x * invK, m1y = s1y * invK, m1z = s1z * invK;
    float m2x = s2x * invK, m2y = s2y * invK, m2z = s2z * invK;

    float k00 = c00 - s1x * m2x, k01 = c01 - s1x * m2y, k02 = c02 - s1x * m2z;
    float k10 = c10 - s1y * m2x, k11 = c11 - s1y * m2y, k12 = c12 - s1y * m2z;
    float k20 = c20 - s1z * m2x, k21 = c21 - s1z * m2y, k22 = c22 - s1z * m2z;
    float var1 = tt - (s1x * m1x + s1y * m1y + s1z * m1z);

    // ---------------- Phase B: 3x3 SVD, redundant per 8-lane group ----------------
    float b00 = k00 * k00 + k10 * k10 + k20 * k20;
    float b01 = k00 * k01 + k10 * k11 + k20 * k21;
    float b02 = k00 * k02 + k10 * k12 + k20 * k22;
    float b11 = k01 * k01 + k11 * k11 + k21 * k21;
    float b12 = k01 * k02 + k11 * k12 + k21 * k22;
    float b22 = k02 * k02 + k12 * k12 + k22 * k22;

    float v00 = 1.f, v01 = 0.f, v02 = 0.f;
    float v10 = 0.f, v11 = 1.f, v12 = 0.f;
    float v20 = 0.f, v21 = 0.f, v22 = 1.f;

#pragma unroll
    for (int sweep = 0; sweep < 4; ++sweep) {
        jrot(b00, b11, b01, b02, b12, v00, v01, v10, v11, v20, v21);
        jrot(b00, b22, b02, b01, b12, v00, v02, v10, v12, v20, v22);
        jrot(b11, b22, b12, b01, b02, v01, v02, v11, v12, v21, v22);
    }

    if (b00 < b11) CSWAP(b00, b11, v00, v01, v10, v11, v20, v21);
    if (b00 < b22) CSWAP(b00, b22, v00, v02, v10, v12, v20, v22);
    if (b11 < b22) CSWAP(b11, b22, v01, v02, v11, v12, v21, v22);

    // rs_i = 1/sigma_i; sigma_i = b_ii * rs_i  (one MUFU serves both)
    float rs0 = rsqrtf(fmaxf(b00, 1e-30f));
    float rs1 = rsqrtf(fmaxf(b11, 1e-30f));
    float rs2 = rsqrtf(fmaxf(b22, 1e-30f));
    float s0 = fmaxf(b00, 0.f) * rs0;
    float s1 = fmaxf(b11, 0.f) * rs1;
    float s2 = fmaxf(b22, 0.f) * rs2;

    // u0 = K v0 * rs0 ; u1 = K v1 * rs1
    float a0 = k00 * v00 + k01 * v10 + k02 * v20;
    float a1 = k10 * v00 + k11 * v10 + k12 * v20;
    float a2 = k20 * v00 + k21 * v10 + k22 * v20;
    float u0x = a0 * rs0, u0y = a1 * rs0, u0z = a2 * rs0;

    float e0 = k00 * v01 + k01 * v11 + k02 * v21;
    float e1 = k10 * v01 + k11 * v11 + k12 * v21;
    float e2 = k20 * v01 + k21 * v11 + k22 * v21;
    float u1x = e0 * rs1, u1y = e1 * rs1, u1z = e2 * rs1;

    // u2 from cross product (robust), sign matched to K v2
    float g0 = k00 * v02 + k01 * v12 + k02 * v22;
    float g1 = k10 * v02 + k11 * v12 + k12 * v22;
    float g2 = k20 * v02 + k21 * v12 + k22 * v22;
    float wx = u0y * u1z - u0z * u1y;
    float wy = u0z * u1x - u0x * u1z;
    float wz = u0x * u1y - u0y * u1x;
    float wn = rsqrtf(fmaxf(wx * wx + wy * wy + wz * wz, 1e-30f));
    wx *= wn; wy *= wn; wz *= wn;
    float sgn = (g0 * wx + g1 * wy + g2 * wz) >= 0.f ? 1.f : -1.f;
    float u2x = sgn * wx, u2y = sgn * wy, u2z = sgn * wz;

    // reflection fix: z = sign(det K)
    float detK = k00 * (k11 * k22 - k12 * k21)
               - k01 * (k10 * k22 - k12 * k20)
               + k02 * (k10 * k21 - k11 * k20);
    float z = (detK >= 0.f) ? 1.f : -1.f;

    float scale = __fdividef(s0 + s1 + z * s2, var1);

    // R (scale folded)
    float r00 = scale * (v00 * u0x + v01 * u1x + z * v02 * u2x);
    float r01 = scale * (v00 * u0y + v01 * u1y + z * v02 * u2y);
    float r02 = scale * (v00 * u0z + v01 * u1z + z * v02 * u2z);
    float r10 = scale * (v10 * u0x + v11 * u1x + z * v12 * u2x);
    float r11 = scale * (v10 * u0y + v11 * u1y + z * v12 * u2y);
    float r12 = scale * (v10 * u0z + v11 * u1z + z * v12 * u2z);
    float r20 = scale * (v20 * u0x + v21 * u1x + z * v22 * u2x);
    float r21 = scale * (v20 * u0y + v21 * u1y + z * v22 * u2y);
    float r22 = scale * (v20 * u0z + v21 * u1z + z * v22 * u2z);

    float tr_x = m2x - (r00 * m1x + r01 * m1y + r02 * m1z);
    float tr_y = m2y - (r10 * m1x + r11 * m1y + r12 * m1z);
    float tr_z = m2z - (r20 * m1x + r21 * m1y + r22 * m1z);

    // ---------------- Phase C: residual norms (cache-hot re-read) ----------------
    float lsum = 0.f;
    for (int j = q; j < KPT; j += 8) {
        float tx = pt[3 * j + 0], ty = pt[3 * j + 1], tz = pt[3 * j + 2];
        float ax = tr_x + r00 * tx + r01 * ty + r02 * tz;
        float ay = tr_y + r10 * tx + r11 * ty + r12 * tz;
        float az = tr_z + r20 * tx + r21 * ty + r22 * tz;
        float dx = po[3 * j + 0] - ax;
        float dy = po[3 * j + 1] - ay;
        float dz = po[3 * j + 2] - az;
        float d2 = fmaxf(dx * dx + dy * dy + dz * dz, 1e-30f);
        lsum += d2 * rsqrtf(d2);
    }
    lsum = hsum8(lsum);
    if (!valid) lsum = 0.f;

    // combine 4 groups, one double per warp
    lsum += __shfl_xor_sync(0xffffffffu, lsum, 8);
    lsum += __shfl_xor_sync(0xffffffffu, lsum, 16);
    if (lane == 0)
        g_part[(size_t)blockIdx.x * 4 + warp] = (double)lsum;
}

__global__ void k_reduce1(int nparts)
{
    __shared__ double sh[8];
    int per = (nparts + RED1 - 1) / RED1;
    int lo  = blockIdx.x * per;
    int hi  = min(lo + per, nparts);
    double s = 0.0;
    for (int i = lo + threadIdx.x; i < hi; i += blockDim.x) s += g_part[i];
#pragma unroll
    for (int o = 16; o > 0; o >>= 1) s += __shfl_xor_sync(0xffffffffu, s, o);
    int wi = threadIdx.x >> 5, lane = threadIdx.x & 31;
    if (lane == 0) sh[wi] = s;
    __syncthreads();
    if (threadIdx.x < 32) {
        int nw = blockDim.x >> 5;
        double v = (threadIdx.x < nw) ? sh[threadIdx.x] : 0.0;
#pragma unroll
        for (int o = 4; o > 0; o >>= 1) v += __shfl_xor_sync(0xffffffffu, v, o);
        if (threadIdx.x == 0) g_part2[blockIdx.x] = v;
    }
}

__global__ void k_reduce2(float* __restrict__ out, double inv_cnt)
{
    double v = (threadIdx.x < RED1) ? g_part2[threadIdx.x] : 0.0;
#pragma unroll
    for (int o = 16; o > 0; o >>= 1) v += __shfl_xor_sync(0xffffffffu, v, o);
    if (threadIdx.x == 0) out[0] = (float)(v * inv_cnt);
}

extern "C" void kernel_launch(void* const* d_in, const int* in_sizes, int n_in,
                              void* d_out, int out_size)
{
    const float* g_output = (const float*)d_in[0];
    const float* g_target = (const float*)d_in[1];
    int n = in_sizes[0] / PTS3;

    int blocks = (n + SPB - 1) / SPB;
    k_pa<<<blocks, 128>>>(g_output, g_target, n);
    k_reduce1<<<RED1, 256>>>(blocks * 4);
    double inv_cnt = 1.0 / ((double)n * (double)KPT);
    k_reduce2<<<1, 32>>>((float*)d_out, inv_cnt);
}

// round 6
// speedup vs baseline: 2.5135x; 1.1225x over previous
#include <cuda_runtime.h>
#include <math.h>

#define KPT   133
#define PTS3  399
#define SPW   4             // samples per warp (8 lanes each)
#define SPB   16            // samples per block (4 warps)
#define WFLTS (2 * SPW * PTS3)   // floats staged per warp = 3192
#define NPART (4096 * 4)
#define RED1  32

__device__ double g_part[NPART];
__device__ double g_part2[RED1];

__device__ __forceinline__ float hsum8(float v) {
#pragma unroll
    for (int o = 4; o > 0; o >>= 1) v += __shfl_xor_sync(0xffffffffu, v, o);
    return v;
}

// Exact minimal-angle Jacobi rotation, 2 MUFU, no divisions.
__device__ __forceinline__ void jrot(float& app, float& aqq, float& apq,
                                     float& bkp, float& bkq,
                                     float& vp0, float& vq0,
                                     float& vp1, float& vq1,
                                     float& vp2, float& vq2)
{
    float a  = apq;
    float d  = aqq - app;
    float q2 = d * d + 4.f * a * a;
    float hyp = q2 * rsqrtf(fmaxf(q2, 1e-30f));          // sqrt(d^2+4a^2)
    float ch = fabsf(d) + hyp + 1e-15f;
    float sh = 2.f * a * copysignf(1.f, d);
    float w  = rsqrtf(ch * ch + sh * sh);
    float c  = ch * w;
    float s  = sh * w;
    float cc = c * c, ss = s * s, cs2a = 2.f * c * s * a;
    float napp = cc * app + ss * aqq - cs2a;
    float naqq = ss * app + cc * aqq + cs2a;
    app = napp; aqq = naqq; apq = 0.f;
    float t0 = bkp, t1 = bkq;
    bkp = c * t0 - s * t1;  bkq = s * t0 + c * t1;
    t0 = vp0; t1 = vq0; vp0 = c * t0 - s * t1; vq0 = s * t0 + c * t1;
    t0 = vp1; t1 = vq1; vp1 = c * t0 - s * t1; vq1 = s * t0 + c * t1;
    t0 = vp2; t1 = vq2; vp2 = c * t0 - s * t1; vq2 = s * t0 + c * t1;
}

#define CSWAP(la, lb, x0, x1, y0, y1, z0, z1) \
    { float _t; _t = la; la = lb; lb = _t; _t = x0; x0 = x1; x1 = _t; \
      _t = y0; y0 = y1; y1 = _t; _t = z0; z0 = z1; z1 = _t; }

__global__ void __launch_bounds__(128, 4)
k_pa(const float* __restrict__ g_outp, const float* __restrict__ g_tgtp, int n)
{
    extern __shared__ float sh[];

    const int tid  = threadIdx.x;
    const int warp = tid >> 5;
    const int lane = tid & 31;
    const int grp  = lane >> 3;          // 0..3: sample index within warp
    const int q    = lane & 7;           // lane within the 8-lane sample group

    float* wbase = sh + warp * WFLTS;    // warp-private slab: [o 4x399][t 4x399]

    const int warpS0 = blockIdx.x * SPB + warp * SPW;   // first sample of warp
    const int sample = warpS0 + grp;
    const bool valid = (sample < n);

    // ---------------- Stage: warp-private float4 copy (coalesced) ----------------
    if (warpS0 + SPW <= n) {
        // full fast path: 4x399 floats per array = 399 float4 exactly
        const float4* srcO = (const float4*)(g_outp + (size_t)warpS0 * PTS3);
        const float4* srcT = (const float4*)(g_tgtp + (size_t)warpS0 * PTS3);
        float4* dstO = (float4*)wbase;
        float4* dstT = (float4*)(wbase + SPW * PTS3);
#pragma unroll 4
        for (int i = lane; i < (SPW * PTS3) / 4; i += 32) {
            dstO[i] = srcO[i];
            dstT[i] = srcT[i];
        }
    } else if (warpS0 < n) {
        int nf = (n - warpS0) * PTS3;    // guarded scalar tail copy
        const float* srcO = g_outp + (size_t)warpS0 * PTS3;
        const float* srcT = g_tgtp + (size_t)warpS0 * PTS3;
        for (int i = lane; i < nf; i += 32) {
            wbase[i]              = srcO[i];
            wbase[SPW * PTS3 + i] = srcT[i];
        }
    }
    __syncwarp();

    const float* po = wbase + grp * PTS3;
    const float* pt = wbase + SPW * PTS3 + grp * PTS3;

    // ---------------- Phase A: per-sample sums (8 lanes/sample, LDS) ----------------
    float s1x = 0.f, s1y = 0.f, s1z = 0.f;
    float s2x = 0.f, s2y = 0.f, s2z = 0.f;
    float tt  = 0.f;
    float c00 = 0.f, c01 = 0.f, c02 = 0.f;
    float c10 = 0.f, c11 = 0.f, c12 = 0.f;
    float c20 = 0.f, c21 = 0.f, c22 = 0.f;

#pragma unroll 4
    for (int j = q; j < KPT; j += 8) {
        float ox = po[3 * j + 0], oy = po[3 * j + 1], oz = po[3 * j + 2];
        float tx = pt[3 * j + 0], ty = pt[3 * j + 1], tz = pt[3 * j + 2];
        s2x += ox; s2y += oy; s2z += oz;
        s1x += tx; s1y += ty; s1z += tz;
        tt  += tx * tx + ty * ty + tz * tz;
        c00 += tx * ox; c01 += tx * oy; c02 += tx * oz;
        c10 += ty * ox; c11 += ty * oy; c12 += ty * oz;
        c20 += tz * ox; c21 += tz * oy; c22 += tz * oz;
    }

    s1x = hsum8(s1x); s1y = hsum8(s1y); s1z = hsum8(s1z);
    s2x = hsum8(s2x); s2y = hsum8(s2y); s2z = hsum8(s2z);
    tt  = hsum8(tt);
    c00 = hsum8(c00); c01 = hsum8(c01); c02 = hsum8(c02);
    c10 = hsum8(c10); c11 = hsum8(c11); c12 = hsum8(c12);
    c20 = hsum8(c20); c21 = hsum8(c21); c22 = hsum8(c22);

    const float invK = 1.0f / (float)KPT;
    float m1x = s1x * invK, m1y = s1y * invK, m1z = s1z * invK;
    float m2x = s2x * invK, m2y = s2y * invK, m2z = s2z * invK;

    float k00 = c00 - s1x * m2x, k01 = c01 - s1x * m2y, k02 = c02 - s1x * m2z;
    float k10 = c10 - s1y * m2x, k11 = c11 - s1y * m2y, k12 = c12 - s1y * m2z;
    float k20 = c20 - s1z * m2x, k21 = c21 - s1z * m2y, k22 = c22 - s1z * m2z;
    float var1 = tt - (s1x * m1x + s1y * m1y + s1z * m1z);

    // ---------------- Phase B: 3x3 SVD, redundant per 8-lane group ----------------
    float b00 = k00 * k00 + k10 * k10 + k20 * k20;
    float b01 = k00 * k01 + k10 * k11 + k20 * k21;
    float b02 = k00 * k02 + k10 * k12 + k20 * k22;
    float b11 = k01 * k01 + k11 * k11 + k21 * k21;
    float b12 = k01 * k02 + k11 * k12 + k21 * k22;
    float b22 = k02 * k02 + k12 * k12 + k22 * k22;

    float v00 = 1.f, v01 = 0.f, v02 = 0.f;
    float v10 = 0.f, v11 = 1.f, v12 = 0.f;
    float v20 = 0.f, v21 = 0.f, v22 = 1.f;

#pragma unroll
    for (int sweep = 0; sweep < 4; ++sweep) {
        jrot(b00, b11, b01, b02, b12, v00, v01, v10, v11, v20, v21);
        jrot(b00, b22, b02, b01, b12, v00, v02, v10, v12, v20, v22);
        jrot(b11, b22, b12, b01, b02, v01, v02, v11, v12, v21, v22);
    }

    if (b00 < b11) CSWAP(b00, b11, v00, v01, v10, v11, v20, v21);
    if (b00 < b22) CSWAP(b00, b22, v00, v02, v10, v12, v20, v22);
    if (b11 < b22) CSWAP(b11, b22, v01, v02, v11, v12, v21, v22);

    float rs0 = rsqrtf(fmaxf(b00, 1e-30f));
    float rs1 = rsqrtf(fmaxf(b11, 1e-30f));
    float rs2 = rsqrtf(fmaxf(b22, 1e-30f));
    float s0 = fmaxf(b00, 0.f) * rs0;
    float s1 = fmaxf(b11, 0.f) * rs1;
    float s2 = fmaxf(b22, 0.f) * rs2;

    float a0 = k00 * v00 + k01 * v10 + k02 * v20;
    float a1 = k10 * v00 + k11 * v10 + k12 * v20;
    float a2 = k20 * v00 + k21 * v10 + k22 * v20;
    float u0x = a0 * rs0, u0y = a1 * rs0, u0z = a2 * rs0;

    float e0 = k00 * v01 + k01 * v11 + k02 * v21;
    float e1 = k10 * v01 + k11 * v11 + k12 * v21;
    float e2 = k20 * v01 + k21 * v11 + k22 * v21;
    float u1x = e0 * rs1, u1y = e1 * rs1, u1z = e2 * rs1;

    float g0 = k00 * v02 + k01 * v12 + k02 * v22;
    float g1 = k10 * v02 + k11 * v12 + k12 * v22;
    float g2 = k20 * v02 + k21 * v12 + k22 * v22;
    float wx = u0y * u1z - u0z * u1y;
    float wy = u0z * u1x - u0x * u1z;
    float wz = u0x * u1y - u0y * u1x;
    float wn = rsqrtf(fmaxf(wx * wx + wy * wy + wz * wz, 1e-30f));
    wx *= wn; wy *= wn; wz *= wn;
    float sgn = (g0 * wx + g1 * wy + g2 * wz) >= 0.f ? 1.f : -1.f;
    float u2x = sgn * wx, u2y = sgn * wy, u2z = sgn * wz;

    float detK = k00 * (k11 * k22 - k12 * k21)
               - k01 * (k10 * k22 - k12 * k20)
               + k02 * (k10 * k21 - k11 * k20);
    float z = (detK >= 0.f) ? 1.f : -1.f;

    float scale = __fdividef(s0 + s1 + z * s2, var1);

    float r00 = scale * (v00 * u0x + v01 * u1x + z * v02 * u2x);
    float r01 = scale * (v00 * u0y + v01 * u1y + z * v02 * u2y);
    float r02 = scale * (v00 * u0z + v01 * u1z + z * v02 * u2z);
    float r10 = scale * (v10 * u0x + v11 * u1x + z * v12 * u2x);
    float r11 = scale * (v10 * u0y + v11 * u1y + z * v12 * u2y);
    float r12 = scale * (v10 * u0z + v11 * u1z + z * v12 * u2z);
    float r20 = scale * (v20 * u0x + v21 * u1x + z * v22 * u2x);
    float r21 = scale * (v20 * u0y + v21 * u1y + z * v22 * u2y);
    float r22 = scale * (v20 * u0z + v21 * u1z + z * v22 * u2z);

    float tr_x = m2x - (r00 * m1x + r01 * m1y + r02 * m1z);
    float tr_y = m2y - (r10 * m1x + r11 * m1y + r12 * m1z);
    float tr_z = m2z - (r20 * m1x + r21 * m1y + r22 * m1z);

    // ---------------- Phase C: residual norms (LDS re-read) ----------------
    float lsum = 0.f;
#pragma unroll 4
    for (int j = q; j < KPT; j += 8) {
        float tx = pt[3 * j + 0], ty = pt[3 * j + 1], tz = pt[3 * j + 2];
        float ax = tr_x + r00 * tx + r01 * ty + r02 * tz;
        float ay = tr_y + r10 * tx + r11 * ty + r12 * tz;
        float az = tr_z + r20 * tx + r21 * ty + r22 * tz;
        float dx = po[3 * j + 0] - ax;
        float dy = po[3 * j + 1] - ay;
        float dz = po[3 * j + 2] - az;
        float d2 = fmaxf(dx * dx + dy * dy + dz * dz, 1e-30f);
        lsum += d2 * rsqrtf(d2);
    }
    lsum = hsum8(lsum);
    if (!valid) lsum = 0.f;

    lsum += __shfl_xor_sync(0xffffffffu, lsum, 8);
    lsum += __shfl_xor_sync(0xffffffffu, lsum, 16);
    if (lane == 0)
        g_part[(size_t)blockIdx.x * 4 + warp] = (double)lsum;
}

__global__ void k_reduce1(int nparts)
{
    __shared__ double sh[8];
    int per = (nparts + RED1 - 1) / RED1;
    int lo  = blockIdx.x * per;
    int hi  = min(lo + per, nparts);
    double s = 0.0;
    for (int i = lo + threadIdx.x; i < hi; i += blockDim.x) s += g_part[i];
#pragma unroll
    for (int o = 16; o > 0; o >>= 1) s += __shfl_xor_sync(0xffffffffu, s, o);
    int wi = threadIdx.x >> 5, lane = threadIdx.x & 31;
    if (lane == 0) sh[wi] = s;
    __syncthreads();
    if (threadIdx.x < 32) {
        int nw = blockDim.x >> 5;
        double v = (threadIdx.x < nw) ? sh[threadIdx.x] : 0.0;
#pragma unroll
        for (int o = 4; o > 0; o >>= 1) v += __shfl_xor_sync(0xffffffffu, v, o);
        if (threadIdx.x == 0) g_part2[blockIdx.x] = v;
    }
}

__global__ void k_reduce2(float* __restrict__ out, double inv_cnt)
{
    double v = (threadIdx.x < RED1) ? g_part2[threadIdx.x] : 0.0;
#pragma unroll
    for (int o = 16; o > 0; o >>= 1) v += __shfl_xor_sync(0xffffffffu, v, o);
    if (threadIdx.x == 0) out[0] = (float)(v * inv_cnt);
}

extern "C" void kernel_launch(void* const* d_in, const int* in_sizes, int n_in,
                              void* d_out, int out_size)
{
    const float* g_output = (const float*)d_in[0];
    const float* g_target = (const float*)d_in[1];
    int n = in_sizes[0] / PTS3;

    size_t shbytes = (size_t)4 * WFLTS * sizeof(float);   // 51072 B
    cudaFuncSetAttribute(k_pa, cudaFuncAttributeMaxDynamicSharedMemorySize, (int)shbytes);

    int blocks = (n + SPB - 1) / SPB;
    k_pa<<<blocks, 128, shbytes>>>(g_output, g_target, n);
    k_reduce1<<<RED1, 256>>>(blocks * 4);
    double inv_cnt = 1.0 / ((double)n * (double)KPT);
    k_reduce2<<<1, 32>>>((float*)d_out, inv_cnt);
}